// round 6
// baseline (speedup 1.0000x reference)
#include <cuda_runtime.h>
#include <stdint.h>

#define HOPS 3
#define LBL  10
#define DIM  128
#define WPB  8
#define THREADS (WPB * 32)
#define UNROLL 4
#define GRIDX 148                   // one wave: 148 SMs x 3 blocks/SM = 444 = GRIDX*HOPS

// Scratch (__device__ globals — no allocation allowed)
__device__ float        g_sums[HOPS * LBL * DIM];
__device__ float        g_counts[LBL];
__device__ unsigned int g_done;

// ---------------------------------------------------------------------------
// Kernel 1: zero scratch + ticket.
// ---------------------------------------------------------------------------
__global__ void init_kernel() {
    int i = blockIdx.x * blockDim.x + threadIdx.x;
    if (i < HOPS * LBL * DIM) g_sums[i] = 0.0f;
    if (i < LBL) g_counts[i] = 0.0f;
    if (i == 0) g_done = 0u;
}

// Packed-f32x2 helpers (Blackwell: add.rn.f32x2 only reachable via PTX).
__device__ __forceinline__ unsigned long long pack_f32x2(float lo, float hi) {
    unsigned long long r;
    asm("mov.b64 %0, {%1, %2};" : "=l"(r) : "f"(lo), "f"(hi));
    return r;
}
__device__ __forceinline__ void unpack_f32x2(unsigned long long v, float& lo, float& hi) {
    asm("mov.b64 {%0, %1}, %2;" : "=f"(lo), "=f"(hi) : "l"(v));
}
// if (lab == l) { a0 += v0; a1 += v1; }  — one predicate, two packed adds.
__device__ __forceinline__ void pred_add2(unsigned long long& a0, unsigned long long& a1,
                                          unsigned long long v0, unsigned long long v1,
                                          int lab, int l) {
    asm("{ .reg .pred p;\n\t"
        "  setp.eq.s32 p, %4, %5;\n\t"
        "  @p add.rn.f32x2 %0, %0, %2;\n\t"
        "  @p add.rn.f32x2 %1, %1, %3; }"
        : "+l"(a0), "+l"(a1)
        : "l"(v0), "l"(v1), "r"(lab), "r"(l));
}

// ---------------------------------------------------------------------------
// Hot loop templated on label dtype. One warp per node; accumulators live in
// registers (10 labels x 2 f32x2 per lane). No shared memory in the hot loop.
// ---------------------------------------------------------------------------
template <bool IS64>
__device__ __forceinline__ void hot_loop(const float4* __restrict__ e4,
                                         const void*   __restrict__ labels_raw,
                                         unsigned long long* a0,   // [LBL]
                                         unsigned long long* a1,   // [LBL]
                                         int* __restrict__ scnt,   // smem counters or null
                                         int N, int gw, int nw, int lane) {
    const int*       l32 = reinterpret_cast<const int*>(labels_raw);
    const long long* l64 = reinterpret_cast<const long long*>(labels_raw);

    for (int base = gw * UNROLL; base < N; base += nw * UNROLL) {
        int    lab[UNROLL];
        float4 v[UNROLL];
#pragma unroll
        for (int k = 0; k < UNROLL; k++) {
            int n = base + k;
            if (n < N) {
                lab[k] = IS64 ? (int)l64[n] : l32[n];
                v[k]   = e4[(size_t)n * (DIM / 4) + lane];
            } else {
                lab[k] = -1;
            }
        }
#pragma unroll
        for (int k = 0; k < UNROLL; k++) {
            unsigned long long v0 = pack_f32x2(v[k].x, v[k].y);
            unsigned long long v1 = pack_f32x2(v[k].z, v[k].w);
#pragma unroll
            for (int l = 0; l < LBL; l++)
                pred_add2(a0[l], a1[l], v0, v1, lab[k], l);
            if (scnt && lane == 0 && lab[k] >= 0)
                atomicAdd(&scnt[lab[k]], 1);
        }
    }
}

// ---------------------------------------------------------------------------
// Kernel 2: accumulate (register accs) + last-block finalize. blockIdx.y = hop.
// ---------------------------------------------------------------------------
__global__ void __launch_bounds__(THREADS, 3)
accumulate_kernel(const float* __restrict__ emb,
                  const void*  __restrict__ labels_raw,
                  int N,
                  const float* __restrict__ weight,
                  float* __restrict__ out,
                  int totalBlocks) {
    __shared__ __align__(16) float bank[LBL * DIM];   // 5 KB block-level stage
    __shared__ int scnt[LBL];
    __shared__ int s_not64;
    __shared__ unsigned int s_ticket;

    const int tid  = threadIdx.x;
    const int warp = tid >> 5;
    const int lane = tid & 31;
    const int hop  = blockIdx.y;

    for (int i = tid; i < LBL * DIM; i += THREADS) bank[i] = 0.0f;
    if (tid < LBL) scnt[tid] = 0;
    if (tid == 0) s_not64 = 0;
    __syncthreads();

    // labels dtype detection: int64 (values 0..9, LE) => odd 32-bit words all 0.
    {
        const int* l32 = reinterpret_cast<const int*>(labels_raw);
        int nscan = N / 2; if (nscan > 4096) nscan = 4096;
        for (int j = tid; j < nscan; j += THREADS)
            if (l32[2 * j + 1] != 0) s_not64 = 1;
    }
    __syncthreads();
    const bool is64 = (s_not64 == 0);

    const float4* e4 = reinterpret_cast<const float4*>(emb) + (size_t)hop * N * (DIM / 4);

    unsigned long long a0[LBL], a1[LBL];
#pragma unroll
    for (int l = 0; l < LBL; l++) { a0[l] = 0ull; a1[l] = 0ull; }

    const int gw = blockIdx.x * WPB + warp;
    const int nw = gridDim.x * WPB;
    int* cnt = (hop == 0) ? scnt : nullptr;

    if (is64) hot_loop<true >(e4, labels_raw, a0, a1, cnt, N, gw, nw, lane);
    else      hot_loop<false>(e4, labels_raw, a0, a1, cnt, N, gw, nw, lane);
    __syncthreads();

    // Round-robin: each warp folds its register accs into the shared bank.
    for (int w = 0; w < WPB; w++) {
        if (warp == w) {
#pragma unroll
            for (int l = 0; l < LBL; l++) {
                float x, y, z, ww;
                unpack_f32x2(a0[l], x, y);
                unpack_f32x2(a1[l], z, ww);
                float* p = bank + l * DIM + lane * 4;
                p[0] += x; p[1] += y; p[2] += z; p[3] += ww;
            }
        }
        __syncthreads();
    }

    // One REDG per element per block.
    for (int i = tid; i < LBL * DIM; i += THREADS)
        atomicAdd(&g_sums[hop * LBL * DIM + i], bank[i]);
    if (hop == 0 && tid < LBL && scnt[tid] != 0)
        atomicAdd(&g_counts[tid], (float)scnt[tid]);

    // Last-block ticket -> finalize.
    __threadfence();
    if (tid == 0) s_ticket = atomicAdd(&g_done, 1u);
    __syncthreads();
    if (s_ticket == (unsigned int)(totalBlocks - 1)) {
        for (int i = tid; i < HOPS * LBL * DIM; i += THREADS) {
            int l = (i / DIM) % LBL;
            float c = __ldcg(&g_counts[l]);
            if (c < 1.0f) c = 1.0f;
            out[i] = __ldcg(&g_sums[i]) / c + weight[i];
        }
        if (tid < LBL)
            out[HOPS * LBL * DIM + tid] = __ldcg(&g_counts[tid]);
    }
}

// ---------------------------------------------------------------------------
extern "C" void kernel_launch(void* const* d_in, const int* in_sizes, int n_in,
                              void* d_out, int out_size) {
    const float* emb    = (const float*)d_in[0];   // [3, N, 128] f32
    const void*  labels = d_in[1];                 // [N] int32 or int64
    const float* weight = (const float*)d_in[2];   // [3, 10, 128] f32
    float*       out    = (float*)d_out;           // 3850 f32

    const int N = in_sizes[1];

    init_kernel<<<(HOPS * LBL * DIM + 255) / 256, 256>>>();

    dim3 grid(GRIDX, HOPS, 1);
    accumulate_kernel<<<grid, THREADS>>>(emb, labels, N, weight, out,
                                         GRIDX * HOPS);
}

// round 7
// speedup vs baseline: 1.1705x; 1.1705x over previous
#include <cuda_runtime.h>
#include <stdint.h>

#define HOPS 3
#define LBL  10
#define DIM  128
#define WPB  8
#define THREADS (WPB * 32)
#define UNROLL 4
#define WORK  64                   // nodes per warp ticket grab
#define GRIDX 246                  // per hop; 3*246=738 ~= 148 SMs * 5 blocks

// Scratch (__device__ globals — no allocation allowed)
__device__ float        g_sums[HOPS * LBL * DIM];
__device__ float        g_counts[LBL];
__device__ unsigned int g_done;
__device__ int          g_work[HOPS];

// ---------------------------------------------------------------------------
// Kernel 1: zero scratch + tickets.
// ---------------------------------------------------------------------------
__global__ void init_kernel() {
    int i = blockIdx.x * blockDim.x + threadIdx.x;
    if (i < HOPS * LBL * DIM) g_sums[i] = 0.0f;
    if (i < LBL) g_counts[i] = 0.0f;
    if (i < HOPS) g_work[i] = 0;
    if (i == 0) g_done = 0u;
}

// ---------------------------------------------------------------------------
// Hot loop templated on label dtype. One warp per node: 32 lanes read the
// 512B row as float4 (coalesced); label is warp-uniform -> conflict-free
// per-warp smem bank RMW. Work-stealing: warps grab WORK-node chunks from a
// per-hop global ticket, so no CTA carries a fixed share (kills tail spread).
// ---------------------------------------------------------------------------
template <bool IS64>
__device__ __forceinline__ void hot_loop(const float4* __restrict__ e4,
                                         const void*   __restrict__ labels_raw,
                                         float* __restrict__ my,     // warp acc bank
                                         int* __restrict__ mycnt,    // warp counts or null
                                         int N, int hop, int lane) {
    const int*       l32 = reinterpret_cast<const int*>(labels_raw);
    const long long* l64 = reinterpret_cast<const long long*>(labels_raw);

    for (;;) {
        int start = 0;
        if (lane == 0) start = atomicAdd(&g_work[hop], WORK);
        start = __shfl_sync(0xffffffffu, start, 0);
        if (start >= N) break;
        int end = start + WORK; if (end > N) end = N;

        for (int base = start; base < end; base += UNROLL) {
            int    lab[UNROLL];
            float4 v[UNROLL];
#pragma unroll
            for (int k = 0; k < UNROLL; k++) {
                int n = base + k;
                if (n < end) {
                    lab[k] = IS64 ? (int)l64[n] : l32[n];
                    v[k]   = e4[(size_t)n * (DIM / 4) + lane];
                } else {
                    lab[k] = -1;
                }
            }
#pragma unroll
            for (int k = 0; k < UNROLL; k++) {
                if (lab[k] >= 0) {
                    float4* p = reinterpret_cast<float4*>(my + lab[k] * DIM + lane * 4);
                    float4 cur = *p;
                    cur.x += v[k].x; cur.y += v[k].y; cur.z += v[k].z; cur.w += v[k].w;
                    *p = cur;
                    if (mycnt && lane == 0) mycnt[lab[k]]++;   // warp-private
                }
            }
        }
    }
}

// ---------------------------------------------------------------------------
// Kernel 2: accumulate + last-block finalize. blockIdx.y = hop.
// ---------------------------------------------------------------------------
__global__ void __launch_bounds__(THREADS, 5)
accumulate_kernel(const float* __restrict__ emb,
                  const void*  __restrict__ labels_raw,
                  int N,
                  const float* __restrict__ weight,
                  float* __restrict__ out,
                  int totalBlocks) {
    __shared__ __align__(16) float acc[WPB * LBL * DIM];  // 40 KB
    __shared__ int scnt[WPB][LBL];
    __shared__ int s_not64;
    __shared__ unsigned int s_ticket;

    const int tid  = threadIdx.x;
    const int warp = tid >> 5;
    const int lane = tid & 31;
    const int hop  = blockIdx.y;

    for (int i = tid; i < WPB * LBL * DIM; i += THREADS) acc[i] = 0.0f;
    if (tid < WPB * LBL) scnt[tid / LBL][tid % LBL] = 0;
    if (tid == 0) s_not64 = 0;
    __syncthreads();

    // labels dtype detection: int64 labels (values 0..9, LE) => odd words all 0.
    {
        const int* l32 = reinterpret_cast<const int*>(labels_raw);
        int nscan = N / 2; if (nscan > 4096) nscan = 4096;
        for (int j = tid; j < nscan; j += THREADS)
            if (l32[2 * j + 1] != 0) s_not64 = 1;
    }
    __syncthreads();
    const bool is64 = (s_not64 == 0);

    const float4* e4 = reinterpret_cast<const float4*>(emb) + (size_t)hop * N * (DIM / 4);
    float* my    = acc + warp * LBL * DIM;
    int*   mycnt = (hop == 0) ? scnt[warp] : nullptr;

    if (is64) hot_loop<true >(e4, labels_raw, my, mycnt, N, hop, lane);
    else      hot_loop<false>(e4, labels_raw, my, mycnt, N, hop, lane);
    __syncthreads();

    // Block reduce 8 warp banks; one REDG per (label,dim) per block.
    for (int i = tid; i < LBL * DIM; i += THREADS) {
        float s = 0.0f;
#pragma unroll
        for (int w = 0; w < WPB; w++) s += acc[w * LBL * DIM + i];
        atomicAdd(&g_sums[hop * LBL * DIM + i], s);
    }
    if (hop == 0 && tid < LBL) {
        int c = 0;
#pragma unroll
        for (int w = 0; w < WPB; w++) c += scnt[w][tid];
        if (c) atomicAdd(&g_counts[tid], (float)c);
    }

    // Last-block ticket -> finalize.
    __threadfence();
    if (tid == 0) s_ticket = atomicAdd(&g_done, 1u);
    __syncthreads();
    if (s_ticket == (unsigned int)(totalBlocks - 1)) {
        for (int i = tid; i < HOPS * LBL * DIM; i += THREADS) {
            int l = (i / DIM) % LBL;
            float c = __ldcg(&g_counts[l]);
            if (c < 1.0f) c = 1.0f;
            out[i] = __ldcg(&g_sums[i]) / c + weight[i];
        }
        if (tid < LBL)
            out[HOPS * LBL * DIM + tid] = __ldcg(&g_counts[tid]);
    }
}

// ---------------------------------------------------------------------------
extern "C" void kernel_launch(void* const* d_in, const int* in_sizes, int n_in,
                              void* d_out, int out_size) {
    const float* emb    = (const float*)d_in[0];   // [3, N, 128] f32
    const void*  labels = d_in[1];                 // [N] int32 or int64
    const float* weight = (const float*)d_in[2];   // [3, 10, 128] f32
    float*       out    = (float*)d_out;           // 3850 f32

    const int N = in_sizes[1];

    init_kernel<<<(HOPS * LBL * DIM + 255) / 256, 256>>>();

    dim3 grid(GRIDX, HOPS, 1);
    accumulate_kernel<<<grid, THREADS>>>(emb, labels, N, weight, out,
                                         GRIDX * HOPS);
}

// round 8
// speedup vs baseline: 1.2904x; 1.1024x over previous
#include <cuda_runtime.h>
#include <stdint.h>

#define HOPS 3
#define LBL  10
#define DIM  128
#define WPB  8
#define THREADS (WPB * 32)
#define UNROLL 4
#define GRIDX 246                  // per hop; 3*246=738 blocks ~ 148 SMs * 5 CTA/SM

// Scratch (__device__ globals — no allocation allowed)
__device__ float        g_sums[HOPS * LBL * DIM];
__device__ float        g_counts[LBL];
__device__ unsigned int g_done;

// ---------------------------------------------------------------------------
// Kernel 1: zero scratch + ticket.
// ---------------------------------------------------------------------------
__global__ void init_kernel() {
    int i = blockIdx.x * blockDim.x + threadIdx.x;
    if (i < HOPS * LBL * DIM) g_sums[i] = 0.0f;
    if (i < LBL) g_counts[i] = 0.0f;
    if (i == 0) g_done = 0u;
}

// ---------------------------------------------------------------------------
// Hot loop (R4-proven config). One warp per node: 32 lanes read the 512B row
// as float4 (coalesced LDG.128); label is warp-uniform -> conflict-free
// per-warp smem bank RMW. Static grid-stride partition, UNROLL 4 keeps
// oe*MLP_p1 ~ 20 (low cross-CTA L1tex-queue spread).
// ---------------------------------------------------------------------------
template <bool IS64>
__device__ __forceinline__ void hot_loop(const float4* __restrict__ e4,
                                         const void*   __restrict__ labels_raw,
                                         float* __restrict__ my,     // warp acc bank
                                         int* __restrict__ mycnt,    // warp counts or null
                                         int N, int gw, int nw, int lane) {
    const int*       l32 = reinterpret_cast<const int*>(labels_raw);
    const long long* l64 = reinterpret_cast<const long long*>(labels_raw);

    for (int base = gw * UNROLL; base < N; base += nw * UNROLL) {
        int    lab[UNROLL];
        float4 v[UNROLL];
#pragma unroll
        for (int k = 0; k < UNROLL; k++) {
            int n = base + k;
            if (n < N) {
                lab[k] = IS64 ? (int)l64[n] : l32[n];
                v[k]   = e4[(size_t)n * (DIM / 4) + lane];
            } else {
                lab[k] = -1;
            }
        }
#pragma unroll
        for (int k = 0; k < UNROLL; k++) {
            if (lab[k] >= 0) {
                float4* p = reinterpret_cast<float4*>(my + lab[k] * DIM + lane * 4);
                float4 cur = *p;
                cur.x += v[k].x; cur.y += v[k].y; cur.z += v[k].z; cur.w += v[k].w;
                *p = cur;
                if (mycnt && lane == 0) mycnt[lab[k]]++;   // warp-private
            }
        }
    }
}

// ---------------------------------------------------------------------------
// Kernel 2: accumulate + last-block finalize. blockIdx.y = hop.
// ---------------------------------------------------------------------------
__global__ void __launch_bounds__(THREADS, 5)
accumulate_kernel(const float* __restrict__ emb,
                  const void*  __restrict__ labels_raw,
                  int N,
                  const float* __restrict__ weight,
                  float* __restrict__ out,
                  int totalBlocks) {
    __shared__ __align__(16) float acc[WPB * LBL * DIM];  // 40 KB
    __shared__ int scnt[WPB][LBL];
    __shared__ int s_not64;
    __shared__ unsigned int s_ticket;

    const int tid  = threadIdx.x;
    const int warp = tid >> 5;
    const int lane = tid & 31;
    const int hop  = blockIdx.y;

    for (int i = tid; i < WPB * LBL * DIM; i += THREADS) acc[i] = 0.0f;
    if (tid < WPB * LBL) scnt[tid / LBL][tid % LBL] = 0;
    if (tid == 0) s_not64 = 0;
    __syncthreads();

    // labels dtype detection: int64 labels (values 0..9, LE) => odd words all 0.
    {
        const int* l32 = reinterpret_cast<const int*>(labels_raw);
        int nscan = N / 2; if (nscan > 4096) nscan = 4096;
        for (int j = tid; j < nscan; j += THREADS)
            if (l32[2 * j + 1] != 0) s_not64 = 1;
    }
    __syncthreads();
    const bool is64 = (s_not64 == 0);

    const float4* e4 = reinterpret_cast<const float4*>(emb) + (size_t)hop * N * (DIM / 4);
    float* my    = acc + warp * LBL * DIM;
    int*   mycnt = (hop == 0) ? scnt[warp] : nullptr;

    const int gw = blockIdx.x * WPB + warp;
    const int nw = gridDim.x * WPB;

    if (is64) hot_loop<true >(e4, labels_raw, my, mycnt, N, gw, nw, lane);
    else      hot_loop<false>(e4, labels_raw, my, mycnt, N, gw, nw, lane);
    __syncthreads();

    // Block reduce 8 warp banks; one REDG per (label,dim) per block.
    for (int i = tid; i < LBL * DIM; i += THREADS) {
        float s = 0.0f;
#pragma unroll
        for (int w = 0; w < WPB; w++) s += acc[w * LBL * DIM + i];
        atomicAdd(&g_sums[hop * LBL * DIM + i], s);
    }
    if (hop == 0 && tid < LBL) {
        int c = 0;
#pragma unroll
        for (int w = 0; w < WPB; w++) c += scnt[w][tid];
        if (c) atomicAdd(&g_counts[tid], (float)c);
    }

    // Last-block ticket -> finalize.
    __threadfence();
    if (tid == 0) s_ticket = atomicAdd(&g_done, 1u);
    __syncthreads();
    if (s_ticket == (unsigned int)(totalBlocks - 1)) {
        for (int i = tid; i < HOPS * LBL * DIM; i += THREADS) {
            int l = (i / DIM) % LBL;
            float c = __ldcg(&g_counts[l]);
            if (c < 1.0f) c = 1.0f;
            out[i] = __ldcg(&g_sums[i]) / c + weight[i];
        }
        if (tid < LBL)
            out[HOPS * LBL * DIM + tid] = __ldcg(&g_counts[tid]);
    }
}

// ---------------------------------------------------------------------------
extern "C" void kernel_launch(void* const* d_in, const int* in_sizes, int n_in,
                              void* d_out, int out_size) {
    const float* emb    = (const float*)d_in[0];   // [3, N, 128] f32
    const void*  labels = d_in[1];                 // [N] int32 or int64
    const float* weight = (const float*)d_in[2];   // [3, 10, 128] f32
    float*       out    = (float*)d_out;           // 3850 f32

    const int N = in_sizes[1];

    init_kernel<<<(HOPS * LBL * DIM + 255) / 256, 256>>>();

    dim3 grid(GRIDX, HOPS, 1);
    accumulate_kernel<<<grid, THREADS>>>(emb, labels, N, weight, out,
                                         GRIDX * HOPS);
}

// round 9
// speedup vs baseline: 1.3381x; 1.0370x over previous
#include <cuda_runtime.h>
#include <stdint.h>

#define HOPS 3
#define LBL  10
#define DIM  128
#define WPB  10                    // one warp per label
#define THREADS (WPB * 32)
#define WIN  32                    // nodes per window (one label line)
#define GRIDX 196                  // per hop; 3*196=588 ~ 148 SMs * 4 CTA/SM

// Scratch (__device__ globals — no allocation allowed)
__device__ float        g_sums[HOPS * LBL * DIM];
__device__ float        g_counts[LBL];
__device__ unsigned int g_done;

// ---------------------------------------------------------------------------
// Kernel 1: zero scratch + ticket.
// ---------------------------------------------------------------------------
__global__ void init_kernel() {
    int i = blockIdx.x * blockDim.x + threadIdx.x;
    if (i < HOPS * LBL * DIM) g_sums[i] = 0.0f;
    if (i < LBL) g_counts[i] = 0.0f;
    if (i == 0) g_done = 0u;
}

// ---------------------------------------------------------------------------
// Hot loop: warp = one label. Per 32-node window: read 32 labels (1 line,
// L1-hit for 9/10 warps), ballot matches, batch up to 4 row loads (LDG.128,
// coalesced) and FADD into a 4-register accumulator. NO shared memory.
// ---------------------------------------------------------------------------
template <bool IS64>
__device__ __forceinline__ void hot_loop(const float4* __restrict__ e4,
                                         const void*   __restrict__ labels_raw,
                                         int mylabel, int N, int lane,
                                         int firstWin, int winStride,
                                         float& ax, float& ay, float& az, float& aw,
                                         int& mycount) {
    const int*       l32 = reinterpret_cast<const int*>(labels_raw);
    const long long* l64 = reinterpret_cast<const long long*>(labels_raw);

    for (int wbase = firstWin; wbase < N; wbase += winStride) {
        int n = wbase + lane;
        int lab = -1;
        if (n < N) lab = IS64 ? (int)l64[n] : l32[n];

        unsigned mask = __ballot_sync(0xffffffffu, lab == mylabel);
        mycount += __popc(mask);

        while (mask) {
            int idx[4];
#pragma unroll
            for (int k = 0; k < 4; k++) {
                if (mask) { idx[k] = __ffs(mask) - 1; mask &= mask - 1; }
                else idx[k] = -1;
            }
            float4 v[4];
#pragma unroll
            for (int k = 0; k < 4; k++)
                if (idx[k] >= 0)
                    v[k] = e4[(size_t)(wbase + idx[k]) * (DIM / 4) + lane];
#pragma unroll
            for (int k = 0; k < 4; k++)
                if (idx[k] >= 0) {
                    ax += v[k].x; ay += v[k].y; az += v[k].z; aw += v[k].w;
                }
        }
    }
}

// ---------------------------------------------------------------------------
// Kernel 2: accumulate + last-block finalize. blockIdx.y = hop.
// ---------------------------------------------------------------------------
__global__ void __launch_bounds__(THREADS, 4)
accumulate_kernel(const float* __restrict__ emb,
                  const void*  __restrict__ labels_raw,
                  int N,
                  const float* __restrict__ weight,
                  float* __restrict__ out,
                  int totalBlocks) {
    __shared__ int s_not64;
    __shared__ unsigned int s_ticket;

    const int tid  = threadIdx.x;
    const int warp = tid >> 5;     // == label for this warp
    const int lane = tid & 31;
    const int hop  = blockIdx.y;

    if (tid == 0) s_not64 = 0;
    __syncthreads();

    // labels dtype detection: int64 labels (values 0..9, LE) => odd words all 0.
    {
        const int* l32 = reinterpret_cast<const int*>(labels_raw);
        int nscan = N / 2; if (nscan > 4096) nscan = 4096;
        for (int j = tid; j < nscan; j += THREADS)
            if (l32[2 * j + 1] != 0) s_not64 = 1;
    }
    __syncthreads();
    const bool is64 = (s_not64 == 0);

    const float4* e4 = reinterpret_cast<const float4*>(emb) + (size_t)hop * N * (DIM / 4);

    float ax = 0.0f, ay = 0.0f, az = 0.0f, aw = 0.0f;
    int mycount = 0;

    const int firstWin  = blockIdx.x * WIN;
    const int winStride = gridDim.x * WIN;

    if (is64) hot_loop<true >(e4, labels_raw, warp, N, lane, firstWin, winStride,
                              ax, ay, az, aw, mycount);
    else      hot_loop<false>(e4, labels_raw, warp, N, lane, firstWin, winStride,
                              ax, ay, az, aw, mycount);

    // Epilogue: one REDG burst per warp (4 floats/lane, spread addresses).
    {
        float* dst = &g_sums[hop * LBL * DIM + warp * DIM + lane * 4];
        atomicAdd(dst + 0, ax);
        atomicAdd(dst + 1, ay);
        atomicAdd(dst + 2, az);
        atomicAdd(dst + 3, aw);
    }
    if (hop == 0 && lane == 0 && mycount != 0)
        atomicAdd(&g_counts[warp], (float)mycount);

    // Last-block ticket -> finalize.
    __threadfence();
    __syncthreads();
    if (tid == 0) s_ticket = atomicAdd(&g_done, 1u);
    __syncthreads();
    if (s_ticket == (unsigned int)(totalBlocks - 1)) {
        for (int i = tid; i < HOPS * LBL * DIM; i += THREADS) {
            int l = (i / DIM) % LBL;
            float c = __ldcg(&g_counts[l]);
            if (c < 1.0f) c = 1.0f;
            out[i] = __ldcg(&g_sums[i]) / c + weight[i];
        }
        if (tid < LBL)
            out[HOPS * LBL * DIM + tid] = __ldcg(&g_counts[tid]);
    }
}

// ---------------------------------------------------------------------------
extern "C" void kernel_launch(void* const* d_in, const int* in_sizes, int n_in,
                              void* d_out, int out_size) {
    const float* emb    = (const float*)d_in[0];   // [3, N, 128] f32
    const void*  labels = d_in[1];                 // [N] int32 or int64
    const float* weight = (const float*)d_in[2];   // [3, 10, 128] f32
    float*       out    = (float*)d_out;           // 3850 f32

    const int N = in_sizes[1];

    init_kernel<<<(HOPS * LBL * DIM + 255) / 256, 256>>>();

    dim3 grid(GRIDX, HOPS, 1);
    accumulate_kernel<<<grid, THREADS>>>(emb, labels, N, weight, out,
                                         GRIDX * HOPS);
}

// round 10
// speedup vs baseline: 1.5051x; 1.1248x over previous
#include <cuda_runtime.h>
#include <stdint.h>

#define HOPS   3
#define LBL    10
#define DIM    128
#define ROWB   512                      // bytes per node row (128 f32)
#define CHUNK  64                       // nodes per pipeline stage
#define STAGES 3
#define STAGE_BYTES (CHUNK * ROWB)      // 32 KB
#define SMEM_STAGE0 1024                // stages start here (barriers below)
#define SMEM_TOTAL  (SMEM_STAGE0 + STAGES * STAGE_BYTES)   // 99328 B
#define WARPS  11                       // 10 consumers (1/label) + 1 producer
#define THREADS (WARPS * 32)
#define GRIDX  98                       // per hop; 98*3=294 ~ 148 SMs * 2 CTA/SM

// Scratch (__device__ globals — no allocation allowed)
__device__ float        g_sums[HOPS * LBL * DIM];
__device__ float        g_counts[LBL];
__device__ unsigned int g_done;

// ---------------------------------------------------------------------------
__global__ void init_kernel() {
    int i = blockIdx.x * blockDim.x + threadIdx.x;
    if (i < HOPS * LBL * DIM) g_sums[i] = 0.0f;
    if (i < LBL) g_counts[i] = 0.0f;
    if (i == 0) g_done = 0u;
}

// --- PTX helpers -----------------------------------------------------------
__device__ __forceinline__ uint32_t smem_u32(const void* p) {
    uint32_t a;
    asm("{ .reg .u64 t; cvta.to.shared.u64 t, %1; cvt.u32.u64 %0, t; }"
        : "=r"(a) : "l"(p));
    return a;
}
#define MBAR_INIT(addr, cnt) \
    asm volatile("mbarrier.init.shared.b64 [%0], %1;" :: "r"(addr), "r"(cnt) : "memory")
#define MBAR_EXPECT_TX(addr, bytes) \
    asm volatile("mbarrier.arrive.expect_tx.shared.b64 _, [%0], %1;" :: "r"(addr), "r"(bytes) : "memory")
#define MBAR_ARRIVE(addr) \
    asm volatile("mbarrier.arrive.shared.b64 _, [%0];" :: "r"(addr) : "memory")
#define MBAR_WAIT(addr, parity) do {                                          \
    uint32_t _m = (addr); uint32_t _p = (parity); uint32_t _d;                \
    asm volatile("{ .reg .pred p;\n\t"                                        \
        "mbarrier.try_wait.parity.acquire.cta.shared::cta.b64 p, [%1], %2;\n\t"\
        "selp.b32 %0, 1, 0, p; }" : "=r"(_d) : "r"(_m), "r"(_p) : "memory");  \
    if (!_d) {                                                                \
        asm volatile("{ .reg .pred P1;\n\t"                                   \
            "W%=:\n\t"                                                        \
            "mbarrier.try_wait.parity.acquire.cta.shared::cta.b64 P1, [%0], %1, 0x989680;\n\t" \
            "@P1 bra.uni D%=;\n\t"                                            \
            "bra.uni W%=;\n\t"                                                \
            "D%=: }" :: "r"(_m), "r"(_p) : "memory");                         \
    }                                                                         \
} while (0)
// 1D bulk copy global->shared (SASS: UBLKCP), complete_tx to mbarrier.
#define BULK_G2S(dst, src, bytes, mbar) \
    asm volatile("cp.async.bulk.shared::cluster.global.mbarrier::complete_tx::bytes [%0], [%1], %2, [%3];" \
        :: "r"(dst), "l"(src), "r"(bytes), "r"(mbar) : "memory")

__device__ __forceinline__ void lds128(uint32_t a, float& x, float& y, float& z, float& w) {
    asm volatile("ld.shared.v4.f32 {%0,%1,%2,%3}, [%4];"
                 : "=f"(x), "=f"(y), "=f"(z), "=f"(w) : "r"(a));
}

// Consume all set bits of mask: batched LDS.128 row reads + register FADD.
__device__ __forceinline__ void eat_mask(unsigned mask, uint32_t rowbase, int lane,
                                         float& ax, float& ay, float& az, float& aw) {
    while (mask) {
        uint32_t a[4]; int nb = 0;
#pragma unroll
        for (int k = 0; k < 4; k++) {
            if (mask) { int idx = __ffs(mask) - 1; mask &= mask - 1;
                        a[k] = rowbase + idx * ROWB + lane * 16; nb = k + 1; }
        }
        float x[4], y[4], z[4], w[4];
#pragma unroll
        for (int k = 0; k < 4; k++) if (k < nb) lds128(a[k], x[k], y[k], z[k], w[k]);
#pragma unroll
        for (int k = 0; k < 4; k++) if (k < nb) { ax += x[k]; ay += y[k]; az += z[k]; aw += w[k]; }
    }
}

// ---------------------------------------------------------------------------
// Pipelined accumulate. blockIdx.y = hop. Warp 10 = producer (cp.async.bulk
// ring, 3 stages x 32 KB). Warps 0-9 = per-label consumers: ballot labels
// (global, L1-hit), LDS.128 matching rows from the stage, accumulate in regs.
// ---------------------------------------------------------------------------
__global__ void __launch_bounds__(THREADS, 2)
accumulate_kernel(const float* __restrict__ emb,
                  const void*  __restrict__ labels_raw,
                  int N,
                  const float* __restrict__ weight,
                  float* __restrict__ out,
                  int totalBlocks) {
    extern __shared__ char smem[];
    const uint32_t sb = smem_u32(smem);
    __shared__ int s_not64;
    __shared__ unsigned int s_ticket;

    const int tid  = threadIdx.x;
    const int warp = tid >> 5;
    const int lane = tid & 31;
    const int hop  = blockIdx.y;

    // mbarriers: full(s)=sb+s*16, empty(s)=sb+s*16+8
    if (tid == 0) {
        for (int s = 0; s < STAGES; s++) {
            MBAR_INIT(sb + s * 16,     1u);    // full: tx-based, 1 arrive
            MBAR_INIT(sb + s * 16 + 8, 10u);   // empty: 10 consumer warps
        }
        s_not64 = 0;
    }
    __syncthreads();

    // labels dtype detection: int64 labels (0..9, LE) => odd 32-bit words all 0.
    {
        const int* l32 = reinterpret_cast<const int*>(labels_raw);
        int nscan = N / 2; if (nscan > 4096) nscan = 4096;
        for (int j = tid; j < nscan; j += THREADS)
            if (l32[2 * j + 1] != 0) s_not64 = 1;
    }
    __syncthreads();
    const bool is64 = (s_not64 == 0);

    const int CHUNKS = (N + CHUNK - 1) / CHUNK;

    if (warp == 10) {
        // ---------------- producer ----------------
        if (lane == 0) {
            int stage = 0, phase = 1;   // phase=1: first STAGES empty-waits pass
            const char* hop_base = reinterpret_cast<const char*>(emb)
                                   + (size_t)hop * N * ROWB;
            for (int c = blockIdx.x; c < CHUNKS; c += gridDim.x) {
                MBAR_WAIT(sb + stage * 16 + 8, phase);
                int base = c * CHUNK;
                int rows = N - base; if (rows > CHUNK) rows = CHUNK;
                uint32_t bytes = (uint32_t)rows * ROWB;
                MBAR_EXPECT_TX(sb + stage * 16, bytes);
                BULK_G2S(sb + SMEM_STAGE0 + stage * STAGE_BYTES,
                         hop_base + (size_t)base * ROWB, bytes, sb + stage * 16);
                if (++stage == STAGES) { stage = 0; phase ^= 1; }
            }
        }
    } else {
        // ---------------- consumers (one label per warp) ----------------
        const int mylabel = warp;
        const int*       l32 = reinterpret_cast<const int*>(labels_raw);
        const long long* l64 = reinterpret_cast<const long long*>(labels_raw);
        float ax = 0.f, ay = 0.f, az = 0.f, aw = 0.f;
        int cnt = 0;
        int stage = 0, phase = 0;

        for (int c = blockIdx.x; c < CHUNKS; c += gridDim.x) {
            int base = c * CHUNK;
            int rows = N - base; if (rows > CHUNK) rows = CHUNK;

            // labels from global (L1-hit for 9/10 warps) — overlaps with TMA
            int la = -1, lb = -1;
            if (lane < rows)      la = is64 ? (int)l64[base + lane]      : l32[base + lane];
            if (32 + lane < rows) lb = is64 ? (int)l64[base + 32 + lane] : l32[base + 32 + lane];
            unsigned m0 = __ballot_sync(0xffffffffu, la == mylabel);
            unsigned m1 = __ballot_sync(0xffffffffu, lb == mylabel);
            cnt += __popc(m0) + __popc(m1);

            MBAR_WAIT(sb + stage * 16, phase);
            uint32_t sbase = sb + SMEM_STAGE0 + stage * STAGE_BYTES;
            eat_mask(m0, sbase,             lane, ax, ay, az, aw);
            eat_mask(m1, sbase + 32 * ROWB, lane, ax, ay, az, aw);
            __syncwarp();
            if (lane == 0) MBAR_ARRIVE(sb + stage * 16 + 8);
            if (++stage == STAGES) { stage = 0; phase ^= 1; }
        }

        // epilogue: spread REDG (each address hit by 98 blocks)
        float* dst = &g_sums[hop * LBL * DIM + mylabel * DIM + lane * 4];
        atomicAdd(dst + 0, ax);
        atomicAdd(dst + 1, ay);
        atomicAdd(dst + 2, az);
        atomicAdd(dst + 3, aw);
        if (hop == 0 && lane == 0 && cnt != 0)
            atomicAdd(&g_counts[mylabel], (float)cnt);
    }

    // ---------------- last-block ticket -> finalize ----------------
    __threadfence();
    __syncthreads();
    if (tid == 0) s_ticket = atomicAdd(&g_done, 1u);
    __syncthreads();
    if (s_ticket == (unsigned int)(totalBlocks - 1)) {
        for (int i = tid; i < HOPS * LBL * DIM; i += THREADS) {
            int l = (i / DIM) % LBL;
            float c = __ldcg(&g_counts[l]);
            if (c < 1.0f) c = 1.0f;
            out[i] = __ldcg(&g_sums[i]) / c + weight[i];
        }
        if (tid < LBL)
            out[HOPS * LBL * DIM + tid] = __ldcg(&g_counts[tid]);
    }
}

// ---------------------------------------------------------------------------
extern "C" void kernel_launch(void* const* d_in, const int* in_sizes, int n_in,
                              void* d_out, int out_size) {
    const float* emb    = (const float*)d_in[0];   // [3, N, 128] f32
    const void*  labels = d_in[1];                 // [N] int32 or int64
    const float* weight = (const float*)d_in[2];   // [3, 10, 128] f32
    float*       out    = (float*)d_out;           // 3850 f32

    const int N = in_sizes[1];

    static bool attr_set = false;
    if (!attr_set) {
        cudaFuncSetAttribute(accumulate_kernel,
                             cudaFuncAttributeMaxDynamicSharedMemorySize, SMEM_TOTAL);
        attr_set = true;
    }

    init_kernel<<<(HOPS * LBL * DIM + 255) / 256, 256>>>();

    dim3 grid(GRIDX, HOPS, 1);
    accumulate_kernel<<<grid, THREADS, SMEM_TOTAL>>>(emb, labels, N, weight, out,
                                                     GRIDX * HOPS);
}